// round 1
// baseline (speedup 1.0000x reference)
#include <cuda_runtime.h>

#define NTOK 16384
#define DIN  512
#define DOUT 512
#define NB   8
#define KK   4608          // DIN * 9 (relu + 8 spline features per input dim)
#define NKT  288           // KK / 16

// Scratch (allocation-free per harness rules)
__device__ __align__(16) float g_F[(size_t)NTOK * KK];   // features [tok][k]
__device__ __align__(16) float g_W[(size_t)KK * DOUT];   // packed weights [k][o]

// ---------------------------------------------------------------------------
// Kernel 1: LayerNorm + feature generation.
// One block per token, 512 threads (one per input dim).
// ---------------------------------------------------------------------------
__global__ __launch_bounds__(512)
void feat_kernel(const float* __restrict__ x,
                 const float* __restrict__ gamma_,
                 const float* __restrict__ beta_)
{
    const int tok = blockIdx.x;
    const int d   = threadIdx.x;
    const float v = x[(size_t)tok * DIN + d];

    __shared__ float red[16];

    // ---- mean ----
    float s = v;
    #pragma unroll
    for (int o = 16; o > 0; o >>= 1) s += __shfl_xor_sync(0xffffffffu, s, o);
    if ((d & 31) == 0) red[d >> 5] = s;
    __syncthreads();
    if (d < 16) {
        float t = red[d];
        #pragma unroll
        for (int o = 8; o > 0; o >>= 1) t += __shfl_xor_sync(0x0000ffffu, t, o);
        if (d == 0) red[0] = t;
    }
    __syncthreads();
    const float mu = red[0] * (1.0f / DIN);
    __syncthreads();

    // ---- variance (two-pass, matches reference) ----
    const float dv = v - mu;
    float s2 = dv * dv;
    #pragma unroll
    for (int o = 16; o > 0; o >>= 1) s2 += __shfl_xor_sync(0xffffffffu, s2, o);
    if ((d & 31) == 0) red[d >> 5] = s2;
    __syncthreads();
    if (d < 16) {
        float t = red[d];
        #pragma unroll
        for (int o = 8; o > 0; o >>= 1) t += __shfl_xor_sync(0x0000ffffu, t, o);
        if (d == 0) red[0] = t;
    }
    __syncthreads();
    const float var = red[0] * (1.0f / DIN);
    const float xn  = dv * rsqrtf(var + 1e-5f) * gamma_[d] + beta_[d];

    // ---- cubic B-spline bases on uniform knots t_i = (i-3)*0.6 - 1.5 ----
    float b[11];
    #pragma unroll
    for (int i = 0; i < 11; i++) {
        const float t0 = (float)(i - 3) * 0.6f + (-1.5f);
        const float t1 = (float)(i - 2) * 0.6f + (-1.5f);
        b[i] = (xn >= t0 && xn < t1) ? 1.0f : 0.0f;
    }
    #pragma unroll
    for (int k = 1; k <= 3; k++) {
        #pragma unroll
        for (int i = 0; i < 11 - k; i++) {
            const float ti   = (float)(i - 3)     * 0.6f + (-1.5f);
            const float ti1  = (float)(i - 2)     * 0.6f + (-1.5f);
            const float tik  = (float)(i + k - 3) * 0.6f + (-1.5f);
            const float tik1 = (float)(i + k - 2) * 0.6f + (-1.5f);
            const float left  = (xn - ti)   * (1.0f / (tik  - ti));
            const float right = (tik1 - xn) * (1.0f / (tik1 - ti1));
            b[i] = left * b[i] + right * b[i + 1];
        }
    }

    // ---- RBF + write features ----
    float* Fp = g_F + (size_t)tok * KK + d * 9;
    Fp[0] = fmaxf(xn, 0.0f);   // ReLU channel (base branch)
    #pragma unroll
    for (int j = 0; j < NB; j++) {
        const float g = -1.5f + (float)j * (3.0f / 7.0f);
        const float u = (xn - g) * (7.0f / 3.0f);
        Fp[1 + j] = b[j] + __expf(-u * u);
    }
}

// ---------------------------------------------------------------------------
// Kernel 2: pack base_weight + spline_weight into g_W[k][o], o contiguous.
// k = d*9 + j : j==0 -> base_weight[o][d], else spline_weight[o][d*8 + j-1]
// ---------------------------------------------------------------------------
__global__ void pack_kernel(const float* __restrict__ bw,
                            const float* __restrict__ sw)
{
    const int idx = blockIdx.x * blockDim.x + threadIdx.x;
    if (idx >= KK * DOUT) return;
    const int o = idx % DOUT;
    const int k = idx / DOUT;
    const int d = k / 9;
    const int j = k % 9;
    const float v = (j == 0) ? bw[(size_t)o * DIN + d]
                             : sw[(size_t)o * (DIN * NB) + d * NB + (j - 1)];
    g_W[idx] = v;
}

// ---------------------------------------------------------------------------
// Kernel 3: SGEMM  C[16384][512] = F[16384][4608] * W[4608][512]
// 128x128 tile, BK=16, 256 threads, 8x8 microtile (4+4 split), FFMA2 inner.
// ---------------------------------------------------------------------------
__global__ __launch_bounds__(256)
void sgemm_kernel(float* __restrict__ C)
{
    __shared__ float As[2][16][132];   // [k][m], padded (132 mod 32 = 4) -> 2-way STS max
    __shared__ float Bs[2][16][128];   // [k][n]

    const float* A = g_F;
    const float* B = g_W;

    const int tid = threadIdx.x;
    const int bm  = blockIdx.y * 128;
    const int bn  = blockIdx.x * 128;

    // A tile loads: 128x16 = 512 float4; thread loads rows a_row and a_row+64
    const int a_row = tid >> 2;            // 0..63
    const int a_col = (tid & 3) << 2;      // 0,4,8,12
    const float* Ap = A + (size_t)(bm + a_row) * KK + a_col;

    // B tile loads: 16x128 = 512 float4; thread loads rows b_row and b_row+8
    const int b_row = tid >> 5;            // 0..7
    const int b_col = (tid & 31) << 2;     // 0..124
    const float* Bp = B + (size_t)b_row * 512 + bn + b_col;

    const int tx = tid & 15;               // output col group
    const int ty = tid >> 4;               // output row group

    // accumulators as packed f32x2 pairs: acc[i][jp] = (col 2jp, col 2jp+1)
    unsigned long long acc[8][4];
    #pragma unroll
    for (int i = 0; i < 8; i++)
        #pragma unroll
        for (int jp = 0; jp < 4; jp++) acc[i][jp] = 0ull;

    // prologue: stage tile 0
    float4 ra0 = *(const float4*)(Ap);
    float4 ra1 = *(const float4*)(Ap + (size_t)64 * KK);
    float4 rb0 = *(const float4*)(Bp);
    float4 rb1 = *(const float4*)(Bp + 8 * 512);

    int buf = 0;
    for (int kt = 0; kt < NKT; kt++) {
        // store staged tile into smem[buf] (A transposed)
        As[buf][a_col + 0][a_row]      = ra0.x;
        As[buf][a_col + 1][a_row]      = ra0.y;
        As[buf][a_col + 2][a_row]      = ra0.z;
        As[buf][a_col + 3][a_row]      = ra0.w;
        As[buf][a_col + 0][a_row + 64] = ra1.x;
        As[buf][a_col + 1][a_row + 64] = ra1.y;
        As[buf][a_col + 2][a_row + 64] = ra1.z;
        As[buf][a_col + 3][a_row + 64] = ra1.w;
        *(float4*)&Bs[buf][b_row][b_col]     = rb0;
        *(float4*)&Bs[buf][b_row + 8][b_col] = rb1;
        __syncthreads();

        // prefetch next tile into registers (hidden under compute)
        if (kt + 1 < NKT) {
            const float* Ap2 = Ap + (kt + 1) * 16;
            ra0 = *(const float4*)(Ap2);
            ra1 = *(const float4*)(Ap2 + (size_t)64 * KK);
            const float* Bp2 = Bp + (size_t)(kt + 1) * 16 * 512;
            rb0 = *(const float4*)(Bp2);
            rb1 = *(const float4*)(Bp2 + 8 * 512);
        }

        // compute on smem[buf]
        #pragma unroll
        for (int k = 0; k < 16; k++) {
            const float4 a0 = *(const float4*)&As[buf][k][ty * 4];
            const float4 a1 = *(const float4*)&As[buf][k][64 + ty * 4];
            const ulonglong2 bq0 = *(const ulonglong2*)&Bs[buf][k][tx * 4];
            const ulonglong2 bq1 = *(const ulonglong2*)&Bs[buf][k][64 + tx * 4];
            const unsigned long long bp0 = bq0.x, bp1 = bq0.y, bp2 = bq1.x, bp3 = bq1.y;
            const float av[8] = {a0.x, a0.y, a0.z, a0.w, a1.x, a1.y, a1.z, a1.w};
            #pragma unroll
            for (int i = 0; i < 8; i++) {
                unsigned long long ad;
                asm("mov.b64 %0, {%1, %1};" : "=l"(ad) : "f"(av[i]));
                asm("fma.rn.f32x2 %0, %1, %2, %0;" : "+l"(acc[i][0]) : "l"(ad), "l"(bp0));
                asm("fma.rn.f32x2 %0, %1, %2, %0;" : "+l"(acc[i][1]) : "l"(ad), "l"(bp1));
                asm("fma.rn.f32x2 %0, %1, %2, %0;" : "+l"(acc[i][2]) : "l"(ad), "l"(bp2));
                asm("fma.rn.f32x2 %0, %1, %2, %0;" : "+l"(acc[i][3]) : "l"(ad), "l"(bp3));
            }
        }
        buf ^= 1;
    }

    // epilogue: packed pairs already match memory order of 4 consecutive floats
    float* Cp = C + (size_t)bm * 512 + bn;
    #pragma unroll
    for (int i = 0; i < 8; i++) {
        const int r = (i < 4) ? (ty * 4 + i) : (64 + ty * 4 + (i - 4));
        ulonglong2 v0; v0.x = acc[i][0]; v0.y = acc[i][1];
        ulonglong2 v1; v1.x = acc[i][2]; v1.y = acc[i][3];
        *(ulonglong2*)&Cp[(size_t)r * 512 + tx * 4]      = v0;
        *(ulonglong2*)&Cp[(size_t)r * 512 + 64 + tx * 4] = v1;
    }
}

// ---------------------------------------------------------------------------
extern "C" void kernel_launch(void* const* d_in, const int* in_sizes, int n_in,
                              void* d_out, int out_size)
{
    const float* x  = (const float*)d_in[0];
    const float* g  = (const float*)d_in[1];
    const float* bt = (const float*)d_in[2];
    const float* bw = (const float*)d_in[3];
    const float* sw = (const float*)d_in[4];
    float* out = (float*)d_out;

    feat_kernel<<<NTOK, 512>>>(x, g, bt);
    pack_kernel<<<(KK * DOUT + 255) / 256, 256>>>(bw, sw);
    sgemm_kernel<<<dim3(4, 128), 256>>>(out);
}

// round 2
// speedup vs baseline: 1.0007x; 1.0007x over previous
#include <cuda_runtime.h>

#define NTOK 16384
#define DIN  512
#define DOUT 512
#define NB   8
#define KK   4608          // DIN * 9 (relu + 8 spline features per input dim)
#define NKT  288           // KK / 16

// Scratch (allocation-free per harness rules)
__device__ __align__(16) float g_F[(size_t)NTOK * KK];   // features [tok][k]
__device__ __align__(16) float g_W[(size_t)KK * DOUT];   // packed weights [k][o]

// ---------------------------------------------------------------------------
// Kernel 1: LayerNorm + feature generation.
// One block per token, 512 threads (one per input dim).
// ---------------------------------------------------------------------------
__global__ __launch_bounds__(512)
void feat_kernel(const float* __restrict__ x,
                 const float* __restrict__ gamma_,
                 const float* __restrict__ beta_)
{
    const int tok = blockIdx.x;
    const int d   = threadIdx.x;
    const float v = x[(size_t)tok * DIN + d];

    __shared__ float red[16];

    // ---- mean ----
    float s = v;
    #pragma unroll
    for (int o = 16; o > 0; o >>= 1) s += __shfl_xor_sync(0xffffffffu, s, o);
    if ((d & 31) == 0) red[d >> 5] = s;
    __syncthreads();
    if (d < 16) {
        float t = red[d];
        #pragma unroll
        for (int o = 8; o > 0; o >>= 1) t += __shfl_xor_sync(0x0000ffffu, t, o);
        if (d == 0) red[0] = t;
    }
    __syncthreads();
    const float mu = red[0] * (1.0f / DIN);
    __syncthreads();

    // ---- variance (two-pass, matches reference) ----
    const float dv = v - mu;
    float s2 = dv * dv;
    #pragma unroll
    for (int o = 16; o > 0; o >>= 1) s2 += __shfl_xor_sync(0xffffffffu, s2, o);
    if ((d & 31) == 0) red[d >> 5] = s2;
    __syncthreads();
    if (d < 16) {
        float t = red[d];
        #pragma unroll
        for (int o = 8; o > 0; o >>= 1) t += __shfl_xor_sync(0x0000ffffu, t, o);
        if (d == 0) red[0] = t;
    }
    __syncthreads();
    const float var = red[0] * (1.0f / DIN);
    const float xn  = dv * rsqrtf(var + 1e-5f) * gamma_[d] + beta_[d];

    // ---- cubic B-spline bases on uniform knots t_i = (i-3)*0.6 - 1.5 ----
    float b[11];
    #pragma unroll
    for (int i = 0; i < 11; i++) {
        const float t0 = (float)(i - 3) * 0.6f + (-1.5f);
        const float t1 = (float)(i - 2) * 0.6f + (-1.5f);
        b[i] = (xn >= t0 && xn < t1) ? 1.0f : 0.0f;
    }
    #pragma unroll
    for (int k = 1; k <= 3; k++) {
        #pragma unroll
        for (int i = 0; i < 11 - k; i++) {
            const float ti   = (float)(i - 3)     * 0.6f + (-1.5f);
            const float ti1  = (float)(i - 2)     * 0.6f + (-1.5f);
            const float tik  = (float)(i + k - 3) * 0.6f + (-1.5f);
            const float tik1 = (float)(i + k - 2) * 0.6f + (-1.5f);
            const float left  = (xn - ti)   * (1.0f / (tik  - ti));
            const float right = (tik1 - xn) * (1.0f / (tik1 - ti1));
            b[i] = left * b[i] + right * b[i + 1];
        }
    }

    // ---- RBF + write features ----
    float* Fp = g_F + (size_t)tok * KK + d * 9;
    Fp[0] = fmaxf(xn, 0.0f);   // ReLU channel (base branch)
    #pragma unroll
    for (int j = 0; j < NB; j++) {
        const float g = -1.5f + (float)j * (3.0f / 7.0f);
        const float u = (xn - g) * (7.0f / 3.0f);
        Fp[1 + j] = b[j] + __expf(-u * u);
    }
}

// ---------------------------------------------------------------------------
// Kernel 2: pack base_weight + spline_weight into g_W[k][o], o contiguous.
// k = d*9 + j : j==0 -> base_weight[o][d], else spline_weight[o][d*8 + j-1]
// ---------------------------------------------------------------------------
__global__ void pack_kernel(const float* __restrict__ bw,
                            const float* __restrict__ sw)
{
    const int idx = blockIdx.x * blockDim.x + threadIdx.x;
    if (idx >= KK * DOUT) return;
    const int o = idx % DOUT;
    const int k = idx / DOUT;
    const int d = k / 9;
    const int j = k % 9;
    const float v = (j == 0) ? bw[(size_t)o * DIN + d]
                             : sw[(size_t)o * (DIN * NB) + d * NB + (j - 1)];
    g_W[idx] = v;
}

// ---------------------------------------------------------------------------
// Kernel 3: SGEMM  C[16384][512] = F[16384][4608] * W[4608][512]
// 128x128 tile, BK=16, 256 threads, 8x8 microtile (4+4 split), FFMA2 inner.
// ---------------------------------------------------------------------------
__global__ __launch_bounds__(256)
void sgemm_kernel(float* __restrict__ C)
{
    __shared__ float As[2][16][132];   // [k][m], padded (132 mod 32 = 4) -> 2-way STS max
    __shared__ float Bs[2][16][128];   // [k][n]

    const float* A = g_F;
    const float* B = g_W;

    const int tid = threadIdx.x;
    const int bm  = blockIdx.y * 128;
    const int bn  = blockIdx.x * 128;

    // A tile loads: 128x16 = 512 float4; thread loads rows a_row and a_row+64
    const int a_row = tid >> 2;            // 0..63
    const int a_col = (tid & 3) << 2;      // 0,4,8,12
    const float* Ap = A + (size_t)(bm + a_row) * KK + a_col;

    // B tile loads: 16x128 = 512 float4; thread loads rows b_row and b_row+8
    const int b_row = tid >> 5;            // 0..7
    const int b_col = (tid & 31) << 2;     // 0..124
    const float* Bp = B + (size_t)b_row * 512 + bn + b_col;

    const int tx = tid & 15;               // output col group
    const int ty = tid >> 4;               // output row group

    // accumulators as packed f32x2 pairs: acc[i][jp] = (col 2jp, col 2jp+1)
    unsigned long long acc[8][4];
    #pragma unroll
    for (int i = 0; i < 8; i++)
        #pragma unroll
        for (int jp = 0; jp < 4; jp++) acc[i][jp] = 0ull;

    // prologue: stage tile 0
    float4 ra0 = *(const float4*)(Ap);
    float4 ra1 = *(const float4*)(Ap + (size_t)64 * KK);
    float4 rb0 = *(const float4*)(Bp);
    float4 rb1 = *(const float4*)(Bp + 8 * 512);

    int buf = 0;
    for (int kt = 0; kt < NKT; kt++) {
        // store staged tile into smem[buf] (A transposed)
        As[buf][a_col + 0][a_row]      = ra0.x;
        As[buf][a_col + 1][a_row]      = ra0.y;
        As[buf][a_col + 2][a_row]      = ra0.z;
        As[buf][a_col + 3][a_row]      = ra0.w;
        As[buf][a_col + 0][a_row + 64] = ra1.x;
        As[buf][a_col + 1][a_row + 64] = ra1.y;
        As[buf][a_col + 2][a_row + 64] = ra1.z;
        As[buf][a_col + 3][a_row + 64] = ra1.w;
        *(float4*)&Bs[buf][b_row][b_col]     = rb0;
        *(float4*)&Bs[buf][b_row + 8][b_col] = rb1;
        __syncthreads();

        // prefetch next tile into registers (hidden under compute)
        if (kt + 1 < NKT) {
            const float* Ap2 = Ap + (kt + 1) * 16;
            ra0 = *(const float4*)(Ap2);
            ra1 = *(const float4*)(Ap2 + (size_t)64 * KK);
            const float* Bp2 = Bp + (size_t)(kt + 1) * 16 * 512;
            rb0 = *(const float4*)(Bp2);
            rb1 = *(const float4*)(Bp2 + 8 * 512);
        }

        // compute on smem[buf]
        #pragma unroll
        for (int k = 0; k < 16; k++) {
            const float4 a0 = *(const float4*)&As[buf][k][ty * 4];
            const float4 a1 = *(const float4*)&As[buf][k][64 + ty * 4];
            const ulonglong2 bq0 = *(const ulonglong2*)&Bs[buf][k][tx * 4];
            const ulonglong2 bq1 = *(const ulonglong2*)&Bs[buf][k][64 + tx * 4];
            const unsigned long long bp0 = bq0.x, bp1 = bq0.y, bp2 = bq1.x, bp3 = bq1.y;
            const float av[8] = {a0.x, a0.y, a0.z, a0.w, a1.x, a1.y, a1.z, a1.w};
            #pragma unroll
            for (int i = 0; i < 8; i++) {
                unsigned long long ad;
                asm("mov.b64 %0, {%1, %1};" : "=l"(ad) : "f"(av[i]));
                asm("fma.rn.f32x2 %0, %1, %2, %0;" : "+l"(acc[i][0]) : "l"(ad), "l"(bp0));
                asm("fma.rn.f32x2 %0, %1, %2, %0;" : "+l"(acc[i][1]) : "l"(ad), "l"(bp1));
                asm("fma.rn.f32x2 %0, %1, %2, %0;" : "+l"(acc[i][2]) : "l"(ad), "l"(bp2));
                asm("fma.rn.f32x2 %0, %1, %2, %0;" : "+l"(acc[i][3]) : "l"(ad), "l"(bp3));
            }
        }
        buf ^= 1;
    }

    // epilogue: packed pairs already match memory order of 4 consecutive floats
    float* Cp = C + (size_t)bm * 512 + bn;
    #pragma unroll
    for (int i = 0; i < 8; i++) {
        const int r = (i < 4) ? (ty * 4 + i) : (64 + ty * 4 + (i - 4));
        ulonglong2 v0; v0.x = acc[i][0]; v0.y = acc[i][1];
        ulonglong2 v1; v1.x = acc[i][2]; v1.y = acc[i][3];
        *(ulonglong2*)&Cp[(size_t)r * 512 + tx * 4]      = v0;
        *(ulonglong2*)&Cp[(size_t)r * 512 + 64 + tx * 4] = v1;
    }
}

// ---------------------------------------------------------------------------
extern "C" void kernel_launch(void* const* d_in, const int* in_sizes, int n_in,
                              void* d_out, int out_size)
{
    const float* x  = (const float*)d_in[0];
    const float* g  = (const float*)d_in[1];
    const float* bt = (const float*)d_in[2];
    const float* bw = (const float*)d_in[3];
    const float* sw = (const float*)d_in[4];
    float* out = (float*)d_out;

    feat_kernel<<<NTOK, 512>>>(x, g, bt);
    pack_kernel<<<(KK * DOUT + 255) / 256, 256>>>(bw, sw);
    sgemm_kernel<<<dim3(4, 128), 256>>>(out);
}